// round 1
// baseline (speedup 1.0000x reference)
#include <cuda_runtime.h>
#include <cuda_bf16.h>
#include <math.h>

// ---------------------------------------------------------------------------
// Scratch (static device globals — no allocations anywhere)
// ---------------------------------------------------------------------------
#define MAXACT (8*64*128*128)          // 8,388,608 floats (33.5 MB) — largest activation
__device__ float  g_bufA[MAXACT];
__device__ float  g_bufB[MAXACT];
__device__ float  g_part[4194304];     // split-K partials: max 4.19M floats across all split layers
__device__ float  g_wT[14710464];      // all 13 conv weights transposed to (C,9,O)
__device__ int4   g_tIdx[196416];      // sampling tables: 5 resolutions, [k][HW] layout
__device__ float4 g_tW  [196416];
__device__ float  g_vec[8*512];        // pooled features
__device__ float  g_fc1o[8*4096];
__device__ float  g_fc2o[8*4096];

// ---------------------------------------------------------------------------
// Sampling-table kernel: per pixel p and tap k, 4 clamped corner indices and
// 4 bilinear weights with validity folded in. Layout: base + k*HW + p.
// ---------------------------------------------------------------------------
__global__ void make_table_kernel(int H, int base)
{
    int p = blockIdx.x * blockDim.x + threadIdx.x;
    int HW = H * H;
    if (p >= HW) return;
    int y = p / H, x = p % H;
    float c = H * 0.5f - 0.5f;
    const float TWO_PI = 6.283185307179586f;
    const float PI4    = 0.7853981633974483f;
    float t = atan2f((float)x - c, (float)y - c);
    if (t < 0.f) t += TWO_PI;
    t = rintf(t * 10000.f) / 10000.f;

    #pragma unroll
    for (int k = 0; k < 9; k++) {
        float offy, offx;
        if (k == 4) { offy = 0.f; offx = 0.f; }
        else {
            int m = (k < 4) ? k : (k - 1);
            float ay = (float)(1 - k / 3);
            float ax = (float)(1 - k % 3);
            float ang = t + PI4 * (float)m;
            offy = cosf(ang) + ay;
            offx = sinf(ang) + ax;
        }
        float py = (float)(y - 1 + k / 3) + offy;
        float px = (float)(x - 1 + k % 3) + offx;
        float y0f = floorf(py), x0f = floorf(px);
        float wy = py - y0f, wx = px - x0f;
        int y0 = (int)y0f, x0 = (int)x0f;

        int4 ii; float4 ww;
        {
            int yy = y0, xx = x0;
            bool v = (yy >= 0 && yy <= H-1 && xx >= 0 && xx <= H-1);
            int yc = min(max(yy,0),H-1), xc = min(max(xx,0),H-1);
            ii.x = yc*H + xc; ww.x = v ? (1.f-wy)*(1.f-wx) : 0.f;
        }
        {
            int yy = y0, xx = x0+1;
            bool v = (yy >= 0 && yy <= H-1 && xx >= 0 && xx <= H-1);
            int yc = min(max(yy,0),H-1), xc = min(max(xx,0),H-1);
            ii.y = yc*H + xc; ww.y = v ? (1.f-wy)*wx : 0.f;
        }
        {
            int yy = y0+1, xx = x0;
            bool v = (yy >= 0 && yy <= H-1 && xx >= 0 && xx <= H-1);
            int yc = min(max(yy,0),H-1), xc = min(max(xx,0),H-1);
            ii.z = yc*H + xc; ww.z = v ? wy*(1.f-wx) : 0.f;
        }
        {
            int yy = y0+1, xx = x0+1;
            bool v = (yy >= 0 && yy <= H-1 && xx >= 0 && xx <= H-1);
            int yc = min(max(yy,0),H-1), xc = min(max(xx,0),H-1);
            ii.w = yc*H + xc; ww.w = v ? wy*wx : 0.f;
        }
        g_tIdx[base + k*HW + p] = ii;
        g_tW  [base + k*HW + p] = ww;
    }
}

// ---------------------------------------------------------------------------
// Weight transpose: (O,C,3,3) -> (C,9,O) so the conv kernel reads float4
// broadcasts along O.
// ---------------------------------------------------------------------------
__global__ void wt_kernel(const float* __restrict__ w, float* __restrict__ wT, int C, int O)
{
    int i = blockIdx.x * blockDim.x + threadIdx.x;
    int total = O * C * 9;
    if (i >= total) return;
    int o = i / (C*9);
    int r = i % (C*9);
    int cc = r / 9, k = r % 9;
    wT[((size_t)cc*9 + k) * O + o] = w[i];
}

// ---------------------------------------------------------------------------
// Fused deformable conv. Each thread: 1 output pixel (possibly batch-packed)
// x 64 output channels. Input gathers via L1 (__ldg), tables staged in smem,
// weights staged in smem per 4-channel chunk (float4 broadcast reads).
// kSplit>1: writes split-K partial slices (deterministic) without ReLU.
// ---------------------------------------------------------------------------
__global__ void __launch_bounds__(256, 2)
dconv_kernel(const float* __restrict__ in, float* __restrict__ out,
             const float* __restrict__ wT,
             const int4* __restrict__ tIdx, const float4* __restrict__ tW,
             int H, int C, int O, int kSplit, int NB, int fuseRelu)
{
    extern __shared__ char smemRaw[];
    const int HW  = H * H;
    const int TPX = 256 / NB;
    const int tid = threadIdx.x;
    const int pLocal = tid % TPX;
    const int p  = blockIdx.x * TPX + pLocal;
    const int kc = blockIdx.z % kSplit;
    const int bg = blockIdx.z / kSplit;
    const int b  = bg * NB + tid / TPX;
    const int o0 = blockIdx.y * 64;
    const int chunk  = C / kSplit;
    const int cBegin = kc * chunk;
    const int cEnd   = cBegin + chunk;

    int4*   sIdx = (int4*)smemRaw;                       // [9][TPX]
    float4* sW   = (float4*)(smemRaw + (size_t)9*TPX*16);// [9][TPX]
    float*  wbuf = (float*) (smemRaw + (size_t)9*TPX*32);// [4*9*64]

    // stage sampling tables (coalesced: global layout is [k][HW])
    for (int i = tid; i < 9*TPX; i += 256) {
        int k = i / TPX, pp = i % TPX;
        int g = k*HW + blockIdx.x*TPX + pp;
        sIdx[k*TPX + pp] = tIdx[g];
        sW  [k*TPX + pp] = tW[g];
    }

    float acc[64];
    #pragma unroll
    for (int i = 0; i < 64; i++) acc[i] = 0.f;

    const float* xb = in + (size_t)b * C * HW;

    for (int c0 = cBegin; c0 < cEnd; c0 += 4) {
        int nc = min(4, cEnd - c0);
        __syncthreads();
        // stage weights for up to 4 channels: (nc,9,64) floats = nc*144 float4
        for (int i = tid; i < nc*144; i += 256) {
            int cc = i / 144, r = i % 144;
            int k = r >> 4, o4 = r & 15;
            ((float4*)wbuf)[i] =
                *(const float4*)(wT + ((size_t)(c0+cc)*9 + k)*O + o0 + o4*4);
        }
        __syncthreads();

        for (int cc = 0; cc < nc; cc++) {
            const float* xc = xb + (size_t)(c0+cc) * HW;
            float s[9];
            #pragma unroll
            for (int k = 0; k < 9; k++) {
                int4   ii = sIdx[k*TPX + pLocal];
                float4 ww = sW  [k*TPX + pLocal];
                s[k] = ww.x*__ldg(xc+ii.x) + ww.y*__ldg(xc+ii.y)
                     + ww.z*__ldg(xc+ii.z) + ww.w*__ldg(xc+ii.w);
            }
            const float4* wb4 = (const float4*)(wbuf + cc*576);
            #pragma unroll
            for (int k = 0; k < 9; k++) {
                float sk = s[k];
                #pragma unroll
                for (int o4 = 0; o4 < 16; o4++) {
                    float4 w4 = wb4[k*16 + o4];
                    acc[o4*4+0] = fmaf(sk, w4.x, acc[o4*4+0]);
                    acc[o4*4+1] = fmaf(sk, w4.y, acc[o4*4+1]);
                    acc[o4*4+2] = fmaf(sk, w4.z, acc[o4*4+2]);
                    acc[o4*4+3] = fmaf(sk, w4.w, acc[o4*4+3]);
                }
            }
        }
    }

    size_t sliceOff = (size_t)kc * 8 * O * HW;   // kc==0 when kSplit==1
    float* op = out + sliceOff + (size_t)b*O*HW + (size_t)o0*HW + p;
    if (fuseRelu) {
        #pragma unroll
        for (int o = 0; o < 64; o++) op[(size_t)o*HW] = fmaxf(acc[o], 0.f);
    } else {
        #pragma unroll
        for (int o = 0; o < 64; o++) op[(size_t)o*HW] = acc[o];
    }
}

// ---------------------------------------------------------------------------
// Split-K reduce + ReLU (deterministic).
// ---------------------------------------------------------------------------
__global__ void reduce_relu_kernel(const float* __restrict__ part, float* __restrict__ out,
                                   int n, int kSplit)
{
    int i = blockIdx.x * blockDim.x + threadIdx.x;
    if (i >= n) return;
    float s = 0.f;
    for (int j = 0; j < kSplit; j++) s += part[(size_t)j*n + i];
    out[i] = fmaxf(s, 0.f);
}

// ---------------------------------------------------------------------------
// 2x2 max pool
// ---------------------------------------------------------------------------
__global__ void pool_kernel(const float* __restrict__ in, float* __restrict__ out,
                            int C, int H)
{
    int Ho = H / 2;
    int total = 8 * C * Ho * Ho;
    int i = blockIdx.x * blockDim.x + threadIdx.x;
    if (i >= total) return;
    int xo = i % Ho; int t = i / Ho;
    int yo = t % Ho; t /= Ho;
    int cc = t % C;  int b = t / C;
    const float* base = in + (((size_t)b*C + cc)*H + yo*2)*H + xo*2;
    out[i] = fmaxf(fmaxf(base[0], base[1]), fmaxf(base[H], base[H+1]));
}

// (8,512,4,4) -> (8,512) mean
__global__ void avg_kernel(const float* __restrict__ in, float* __restrict__ out)
{
    int i = blockIdx.x * blockDim.x + threadIdx.x;
    if (i >= 8*512) return;
    const float* p = in + (size_t)i * 16;
    float s = 0.f;
    #pragma unroll
    for (int j = 0; j < 16; j++) s += p[j];
    out[i] = s * (1.f/16.f);
}

// ---------------------------------------------------------------------------
// FC: y[b][o] = relu?(sum_k x[b][k]*W[o][k] + bias[o]); one block per o,
// coalesced weight reads, smem reduction. Batch B=8 in registers.
// ---------------------------------------------------------------------------
__global__ void fc_kernel(const float* __restrict__ x, const float* __restrict__ W,
                          const float* __restrict__ bias, float* __restrict__ y,
                          int K, int O, int relu)
{
    int o = blockIdx.x;
    float acc[8];
    #pragma unroll
    for (int i = 0; i < 8; i++) acc[i] = 0.f;
    const float* wr = W + (size_t)o * K;
    for (int k = threadIdx.x; k < K; k += 128) {
        float wv = wr[k];
        #pragma unroll
        for (int b = 0; b < 8; b++) acc[b] = fmaf(x[(size_t)b*K + k], wv, acc[b]);
    }
    __shared__ float red[8][128];
    #pragma unroll
    for (int b = 0; b < 8; b++) red[b][threadIdx.x] = acc[b];
    __syncthreads();
    for (int s = 64; s > 0; s >>= 1) {
        if (threadIdx.x < s) {
            #pragma unroll
            for (int b = 0; b < 8; b++)
                red[b][threadIdx.x] += red[b][threadIdx.x + s];
        }
        __syncthreads();
    }
    if (threadIdx.x < 8) {
        int b = threadIdx.x;
        float v = red[b][0] + bias[o];
        if (relu) v = fmaxf(v, 0.f);
        y[(size_t)b*O + o] = v;
    }
}

// ---------------------------------------------------------------------------
// Host orchestration
// ---------------------------------------------------------------------------
extern "C" void kernel_launch(void* const* d_in, const int* in_sizes, int n_in,
                              void* d_out, int out_size)
{
    const float* x = (const float*)d_in[0];
    const float* w[13];
    for (int i = 0; i < 13; i++) w[i] = (const float*)d_in[1+i];
    const float* fc1w = (const float*)d_in[14];
    const float* fc1b = (const float*)d_in[15];
    const float* fc2w = (const float*)d_in[16];
    const float* fc2b = (const float*)d_in[17];
    const float* fc3w = (const float*)d_in[18];
    const float* fc3b = (const float*)d_in[19];

    float *bufA, *bufB, *part, *wT, *vec, *f1, *f2;
    int4* tI; float4* tWt;
    cudaGetSymbolAddress((void**)&bufA, g_bufA);
    cudaGetSymbolAddress((void**)&bufB, g_bufB);
    cudaGetSymbolAddress((void**)&part, g_part);
    cudaGetSymbolAddress((void**)&wT,   g_wT);
    cudaGetSymbolAddress((void**)&tI,   g_tIdx);
    cudaGetSymbolAddress((void**)&tWt,  g_tW);
    cudaGetSymbolAddress((void**)&vec,  g_vec);
    cudaGetSymbolAddress((void**)&f1,   g_fc1o);
    cudaGetSymbolAddress((void**)&f2,   g_fc2o);

    cudaFuncSetAttribute(dconv_kernel, cudaFuncAttributeMaxDynamicSharedMemorySize, 82944);

    // --- sampling tables (per resolution) ---
    const int resz[5]  = {128, 64, 32, 16, 8};
    const int tbase[5] = {0, 147456, 184320, 193536, 195840};
    for (int i = 0; i < 5; i++) {
        int hw = resz[i]*resz[i];
        make_table_kernel<<<(hw + 255)/256, 256>>>(resz[i], tbase[i]);
    }

    // --- weight transposes ---
    struct LCfg { int C, O; };
    const LCfg lw[13] = {{3,64},{64,64},{64,128},{128,128},{128,256},{256,256},{256,256},
                         {256,512},{512,512},{512,512},{512,512},{512,512},{512,512}};
    size_t woff[13]; size_t wacc = 0;
    for (int i = 0; i < 13; i++) {
        woff[i] = wacc;
        int total = lw[i].O * lw[i].C * 9;
        wt_kernel<<<(total + 255)/256, 256>>>(w[i], wT + woff[i], lw[i].C, lw[i].O);
        wacc += (size_t)total;
    }

    auto tbl = [&](int H) {
        int idx = (H==128)?0:(H==64)?1:(H==32)?2:(H==16)?3:4;
        return idx;
    };

    auto conv = [&](const float* in_, float* out_, int li, int H, int kSplit, int NB) {
        int C = lw[li].C, O = lw[li].O;
        int HW = H*H, TPX = 256/NB;
        dim3 grid(HW/TPX, O/64, (8/NB)*kSplit);
        size_t smem = (size_t)9*TPX*32 + 9216;
        int ti = tbl(H);
        if (kSplit == 1) {
            dconv_kernel<<<grid, 256, smem>>>(in_, out_, wT + woff[li],
                                              tI + tbase[ti], tWt + tbase[ti],
                                              H, C, O, 1, NB, 1);
        } else {
            dconv_kernel<<<grid, 256, smem>>>(in_, part, wT + woff[li],
                                              tI + tbase[ti], tWt + tbase[ti],
                                              H, C, O, kSplit, NB, 0);
            int n = 8*O*HW;
            reduce_relu_kernel<<<(n + 255)/256, 256>>>(part, out_, n, kSplit);
        }
    };

    // --- network ---
    conv(x,    bufA, 0, 128, 1, 1);            // L11: (8,64,128,128)
    conv(bufA, bufB, 1, 128, 1, 1);            // L12
    pool_kernel<<<(8*64*64*64 + 255)/256, 256>>>(bufB, bufA, 64, 128);     // -> 64^2

    conv(bufA, bufB, 2, 64, 1, 1);             // L21: (8,128,64,64)
    conv(bufB, bufA, 3, 64, 1, 1);             // L22
    pool_kernel<<<(8*128*32*32 + 255)/256, 256>>>(bufA, bufB, 128, 64);    // -> 32^2

    conv(bufB, bufA, 4, 32, 2, 1);             // L31: (8,256,32,32)
    conv(bufA, bufB, 5, 32, 2, 1);             // L32
    conv(bufB, bufA, 6, 32, 2, 1);             // L33
    pool_kernel<<<(8*256*16*16 + 255)/256, 256>>>(bufA, bufB, 256, 32);    // -> 16^2

    conv(bufB, bufA, 7, 16, 4, 1);             // L41: (8,512,16,16)
    conv(bufA, bufB, 8, 16, 4, 1);             // L42
    conv(bufB, bufA, 9, 16, 4, 1);             // L43
    pool_kernel<<<(8*512*8*8 + 255)/256, 256>>>(bufA, bufB, 512, 16);      // -> 8^2

    conv(bufB, bufA, 10, 8, 16, 4);            // L51: (8,512,8,8)
    conv(bufA, bufB, 11, 8, 16, 4);            // L52
    conv(bufB, bufA, 12, 8, 16, 4);            // L53
    pool_kernel<<<(8*512*4*4 + 255)/256, 256>>>(bufA, bufB, 512, 8);       // -> 4^2

    avg_kernel<<<(8*512 + 255)/256, 256>>>(bufB, vec);                     // (8,512)

    fc_kernel<<<4096, 128>>>(vec, fc1w, fc1b, f1, 512, 4096, 1);
    fc_kernel<<<4096, 128>>>(f1,  fc2w, fc2b, f2, 4096, 4096, 1);
    fc_kernel<<<30,   128>>>(f2,  fc3w, fc3b, (float*)d_out, 4096, 30, 0);
}